// round 1
// baseline (speedup 1.0000x reference)
#include <cuda_runtime.h>
#include <math.h>

#define BB 8
#define D 768
#define NH 12
#define DH 64
#define HW 1024
#define G 5
#define S 1029           // G + HW
#define M_TOT (BB * S)   // 8232

// ---------------- scratch (static device globals; no runtime allocs) ----------
__device__ float g_xwt[(size_t)M_TOT * D];      // LN1 output (residual base)
__device__ float g_qkv[(size_t)M_TOT * 3 * D];
__device__ float g_o  [(size_t)M_TOT * D];      // attention output (pre out_proj)
__device__ float g_y  [(size_t)M_TOT * D];      // o@Wout + b + xwt
__device__ float g_z  [(size_t)M_TOT * D];      // LN2(y)
__device__ float g_h  [(size_t)M_TOT * 4 * D];  // gelu(z@W1+b1)
__device__ float g_y2 [(size_t)M_TOT * D];      // final

// ---------------- block reduce (sum, sumsq) over 256 threads -------------------
__device__ __forceinline__ void block_reduce2(float& a, float& b2) {
    #pragma unroll
    for (int o = 16; o > 0; o >>= 1) {
        a  += __shfl_down_sync(0xFFFFFFFFu, a, o);
        b2 += __shfl_down_sync(0xFFFFFFFFu, b2, o);
    }
    __shared__ float sa[8], sb[8];
    int w = threadIdx.x >> 5, l = threadIdx.x & 31;
    if (l == 0) { sa[w] = a; sb[w] = b2; }
    __syncthreads();
    if (threadIdx.x < 8) {
        a = sa[threadIdx.x]; b2 = sb[threadIdx.x];
        #pragma unroll
        for (int o = 4; o > 0; o >>= 1) {
            a  += __shfl_down_sync(0xFFu, a, o);
            b2 += __shfl_down_sync(0xFFu, b2, o);
        }
        if (threadIdx.x == 0) { sa[0] = a; sb[0] = b2; }
    }
    __syncthreads();
    a = sa[0]; b2 = sb[0];
}

// ---------------- K0: build tokens/x_flat, add PE, LayerNorm1 ------------------
__global__ void __launch_bounds__(256) build_xwt_kernel(
    const float* __restrict__ x, const float* __restrict__ ctx,
    const float* __restrict__ regs,
    const float* __restrict__ gs, const float* __restrict__ gb)
{
    int row = blockIdx.x;           // 0..M_TOT-1
    int b = row / S, sIdx = row % S;
    int tid = threadIdx.x;

    float vals[3];
    float s = 0.f, s2 = 0.f;
    #pragma unroll
    for (int i = 0; i < 3; i++) {
        int k = tid + i * 256;
        float v;
        if (sIdx < G) {
            float base = (sIdx == 0) ? ctx[k] : regs[(sIdx - 1) * D + k];
            float expo = (float)(2 * (k / 2)) / (float)D;
            float denom = powf(10000.0f, expo);
            float angle = (float)sIdx / denom;
            float pe = (k & 1) ? cosf(angle) : sinf(angle);
            v = base + pe;
        } else {
            int pix = sIdx - G;
            v = x[((size_t)b * D + k) * HW + pix];
        }
        vals[i] = v;
        s += v; s2 += v * v;
    }
    block_reduce2(s, s2);
    float mean = s * (1.0f / D);
    float var  = s2 * (1.0f / D) - mean * mean;
    float rstd = rsqrtf(var + 1e-5f);
    #pragma unroll
    for (int i = 0; i < 3; i++) {
        int k = tid + i * 256;
        g_xwt[(size_t)row * D + k] = (vals[i] - mean) * rstd * gs[k] + gb[k];
    }
}

// ---------------- generic LN (for LN2) -----------------------------------------
__global__ void __launch_bounds__(256) ln_kernel(
    const float* __restrict__ in, const float* __restrict__ gs,
    const float* __restrict__ gb, float* __restrict__ out)
{
    int row = blockIdx.x;
    const float* p = in + (size_t)row * D;
    int tid = threadIdx.x;
    float vals[3];
    float s = 0.f, s2 = 0.f;
    #pragma unroll
    for (int i = 0; i < 3; i++) {
        float v = p[tid + i * 256];
        vals[i] = v; s += v; s2 += v * v;
    }
    block_reduce2(s, s2);
    float mean = s * (1.0f / D);
    float var  = s2 * (1.0f / D) - mean * mean;
    float rstd = rsqrtf(var + 1e-5f);
    #pragma unroll
    for (int i = 0; i < 3; i++) {
        int k = tid + i * 256;
        out[(size_t)row * D + k] = (vals[i] - mean) * rstd * gs[k] + gb[k];
    }
}

// ---------------- generic SGEMM: C = A[M,K] @ W[N,K]^T + bias (+gelu)(+resid) ---
template<bool GELU, bool RESID>
__global__ void __launch_bounds__(256) sgemm_tn(
    const float* __restrict__ A, const float* __restrict__ W,
    const float* __restrict__ bias, const float* __restrict__ Rz,
    float* __restrict__ C, int Mm, int Nn, int Kk)
{
    __shared__ float As[16][128];
    __shared__ float Bs[16][128];
    int m0 = blockIdx.y * 128, n0 = blockIdx.x * 128;
    int tid = threadIdx.x;
    int tx = tid & 15, ty = tid >> 4;

    float acc[8][8];
    #pragma unroll
    for (int i = 0; i < 8; i++)
        #pragma unroll
        for (int j = 0; j < 8; j++) acc[i][j] = 0.f;

    for (int kt = 0; kt < Kk; kt += 16) {
        #pragma unroll
        for (int i = 0; i < 2; i++) {
            int f = tid + i * 256;       // 0..511
            int row = f >> 2;            // 0..127
            int kk4 = (f & 3) * 4;
            float4 av = make_float4(0.f, 0.f, 0.f, 0.f);
            if (m0 + row < Mm)
                av = *(const float4*)&A[(size_t)(m0 + row) * Kk + kt + kk4];
            As[kk4 + 0][row] = av.x; As[kk4 + 1][row] = av.y;
            As[kk4 + 2][row] = av.z; As[kk4 + 3][row] = av.w;
            float4 bv = make_float4(0.f, 0.f, 0.f, 0.f);
            if (n0 + row < Nn)
                bv = *(const float4*)&W[(size_t)(n0 + row) * Kk + kt + kk4];
            Bs[kk4 + 0][row] = bv.x; Bs[kk4 + 1][row] = bv.y;
            Bs[kk4 + 2][row] = bv.z; Bs[kk4 + 3][row] = bv.w;
        }
        __syncthreads();
        #pragma unroll
        for (int kk = 0; kk < 16; kk++) {
            float a[8], bb[8];
            #pragma unroll
            for (int i = 0; i < 8; i++) a[i] = As[kk][ty * 8 + i];
            #pragma unroll
            for (int j = 0; j < 8; j++) bb[j] = Bs[kk][tx * 8 + j];
            #pragma unroll
            for (int i = 0; i < 8; i++)
                #pragma unroll
                for (int j = 0; j < 8; j++) acc[i][j] += a[i] * bb[j];
        }
        __syncthreads();
    }

    #pragma unroll
    for (int i = 0; i < 8; i++) {
        int m = m0 + ty * 8 + i;
        if (m >= Mm) continue;
        #pragma unroll
        for (int j = 0; j < 8; j++) {
            int n = n0 + tx * 8 + j;
            float c = acc[i][j] + bias[n];
            if (GELU) c = 0.5f * c * (1.0f + erff(c * 0.70710678118654752f));
            if (RESID) c += Rz[(size_t)m * Nn + n];
            C[(size_t)m * Nn + n] = c;
        }
    }
}

// ---------------- fused flash attention (fp32, online softmax) -----------------
__global__ void __launch_bounds__(64) attn_kernel()
{
    int qt = blockIdx.x, h = blockIdx.y, b = blockIdx.z;
    int tid = threadIdx.x;
    int qi = qt * 64 + tid;
    bool active = qi < S;
    bool rowfeat = qi >= G;

    __shared__ float Ks[64][64];
    __shared__ float Vs[64][64];

    float q[DH];
    if (active) {
        const float* qp = g_qkv + ((size_t)b * S + qi) * (3 * D) + h * DH;
        #pragma unroll
        for (int d = 0; d < DH; d++) q[d] = qp[d];
    }
    float acc[DH];
    #pragma unroll
    for (int d = 0; d < DH; d++) acc[d] = 0.f;
    float m_i = -1e30f, l_i = 0.f;

    for (int k0 = 0; k0 < S; k0 += 64) {
        // cooperative coalesced K/V tile load: iteration i loads row i, lane=col
        for (int i = 0; i < 64; i++) {
            int ki = k0 + i;
            float kv = 0.f, vv = 0.f;
            if (ki < S) {
                const float* base = g_qkv + ((size_t)b * S + ki) * (3 * D) + h * DH + tid;
                kv = base[D];
                vv = base[2 * D];
            }
            Ks[i][tid] = kv;
            Vs[i][tid] = vv;
        }
        __syncthreads();

        if (active) {
            #pragma unroll
            for (int c = 0; c < 4; c++) {        // 16-key chunks
                float sc[16];
                float mx = m_i;
                #pragma unroll
                for (int jj = 0; jj < 16; jj++) {
                    int j = c * 16 + jj;
                    int ki = k0 + j;
                    float sv = 0.f;
                    #pragma unroll
                    for (int d = 0; d < DH; d++) sv += q[d] * Ks[j][d];
                    sv *= 0.125f;                 // 1/sqrt(64)
                    if (ki >= S || (rowfeat && ki < G)) sv = -1e30f;
                    sc[jj] = sv;
                    mx = fmaxf(mx, sv);
                }
                float scale = __expf(m_i - mx);
                l_i *= scale;
                #pragma unroll
                for (int d = 0; d < DH; d++) acc[d] *= scale;
                #pragma unroll
                for (int jj = 0; jj < 16; jj++) {
                    int j = c * 16 + jj;
                    float p = __expf(sc[jj] - mx);
                    l_i += p;
                    #pragma unroll
                    for (int d = 0; d < DH; d++) acc[d] += p * Vs[j][d];
                }
                m_i = mx;
            }
        }
        __syncthreads();
    }

    if (active) {
        float inv = 1.0f / l_i;
        float* op = g_o + ((size_t)b * S + qi) * D + h * DH;
        #pragma unroll
        for (int d = 0; d < DH; d++) op[d] = acc[d] * inv;
    }
}

// ---------------- scatter final outputs ----------------------------------------
__global__ void __launch_bounds__(256) scatter_out_kernel(float* __restrict__ out)
{
    int idx = blockIdx.x * 256 + threadIdx.x;
    const int FEAT = BB * D * HW;              // 6291456
    const int CTX  = BB * D;                   // 6144
    const int REG  = BB * 4 * D;               // 24576
    if (idx < FEAT) {
        int b = idx / (D * HW);
        int r = idx % (D * HW);
        int k = r / HW;
        int pix = r % HW;
        out[idx] = g_y2[((size_t)(b * S + G + pix)) * D + k];
    } else if (idx < FEAT + CTX) {
        int i2 = idx - FEAT;
        int b = i2 / D, k = i2 % D;
        out[idx] = g_y2[((size_t)(b * S)) * D + k];
    } else if (idx < FEAT + CTX + REG) {
        int i3 = idx - FEAT - CTX;
        int b = i3 / (4 * D);
        int rr = (i3 / D) % 4;
        int k = i3 % D;
        out[idx] = g_y2[((size_t)(b * S + 1 + rr)) * D + k];
    }
}

// ---------------- host launcher -------------------------------------------------
extern "C" void kernel_launch(void* const* d_in, const int* in_sizes, int n_in,
                              void* d_out, int out_size)
{
    const float* x    = (const float*)d_in[0];
    const float* ctx  = (const float*)d_in[1];
    const float* regs = (const float*)d_in[2];
    const float* wqkv = (const float*)d_in[3];
    const float* bqkv = (const float*)d_in[4];
    const float* wout = (const float*)d_in[5];
    const float* bout = (const float*)d_in[6];
    const float* ln1s = (const float*)d_in[7];
    const float* ln1b = (const float*)d_in[8];
    const float* ln2s = (const float*)d_in[9];
    const float* ln2b = (const float*)d_in[10];
    const float* w1   = (const float*)d_in[11];
    const float* b1   = (const float*)d_in[12];
    const float* w2   = (const float*)d_in[13];
    const float* b2   = (const float*)d_in[14];
    float* out = (float*)d_out;
    (void)in_sizes; (void)n_in; (void)out_size;

    float *xwt, *qkv, *o, *y, *z, *hbuf, *y2;
    cudaGetSymbolAddress((void**)&xwt,  g_xwt);
    cudaGetSymbolAddress((void**)&qkv,  g_qkv);
    cudaGetSymbolAddress((void**)&o,    g_o);
    cudaGetSymbolAddress((void**)&y,    g_y);
    cudaGetSymbolAddress((void**)&z,    g_z);
    cudaGetSymbolAddress((void**)&hbuf, g_h);
    cudaGetSymbolAddress((void**)&y2,   g_y2);

    const int M = M_TOT;                       // 8232
    const int MG = (M + 127) / 128;            // 65

    // K0: tokens + PE + x transpose + LN1
    build_xwt_kernel<<<M, 256>>>(x, ctx, regs, ln1s, ln1b);

    // QKV = xwt @ Wqkv^T + b
    sgemm_tn<false, false><<<dim3(3 * D / 128, MG), 256>>>(
        xwt, wqkv, bqkv, nullptr, qkv, M, 3 * D, D);

    // fused attention -> g_o
    attn_kernel<<<dim3((S + 63) / 64, NH, BB), 64>>>();

    // y = o @ Wout^T + b + xwt
    sgemm_tn<false, true><<<dim3(D / 128, MG), 256>>>(
        o, wout, bout, xwt, y, M, D, D);

    // z = LN2(y)
    ln_kernel<<<M, 256>>>(y, ln2s, ln2b, z);

    // h = gelu(z @ W1^T + b1)
    sgemm_tn<true, false><<<dim3(4 * D / 128, MG), 256>>>(
        z, w1, b1, nullptr, hbuf, M, 4 * D, D);

    // y2 = y + h @ W2^T + b2
    sgemm_tn<false, true><<<dim3(D / 128, MG), 256>>>(
        hbuf, w2, b2, y, y2, M, D, 4 * D);

    // scatter outputs: [feature | context | register]
    const int TOT = BB * D * HW + BB * D + BB * 4 * D;
    scatter_out_kernel<<<(TOT + 255) / 256, 256>>>(out);
}

// round 2
// speedup vs baseline: 1.5356x; 1.5356x over previous
#include <cuda_runtime.h>
#include <math.h>
#include <stdint.h>

#define BB 8
#define D 768
#define NH 12
#define DH 64
#define HW 1024
#define G 5
#define S 1029           // G + HW
#define M_TOT (BB * S)   // 8232

// ---------------- scratch (static device globals; no runtime allocs) ----------
__device__ float g_xwt[(size_t)M_TOT * D];      // LN1 output (residual base)
__device__ float g_qkv[(size_t)M_TOT * 3 * D];
__device__ float g_o  [(size_t)M_TOT * D];      // attention output (pre out_proj)
__device__ float g_y  [(size_t)M_TOT * D];      // o@Wout + b + xwt
__device__ float g_z  [(size_t)M_TOT * D];      // LN2(y)
__device__ float g_h  [(size_t)M_TOT * 4 * D];  // gelu(z@W1+b1)
__device__ float g_y2 [(size_t)M_TOT * D];      // final

__device__ __forceinline__ uint32_t f2tf32(float x) {
    uint32_t r;
    asm("cvt.rna.tf32.f32 %0, %1;" : "=r"(r) : "f"(x));
    return r;
}

// ---------------- block reduce (sum, sumsq) over 256 threads -------------------
__device__ __forceinline__ void block_reduce2(float& a, float& b2) {
    #pragma unroll
    for (int o = 16; o > 0; o >>= 1) {
        a  += __shfl_down_sync(0xFFFFFFFFu, a, o);
        b2 += __shfl_down_sync(0xFFFFFFFFu, b2, o);
    }
    __shared__ float sa[8], sb[8];
    int w = threadIdx.x >> 5, l = threadIdx.x & 31;
    if (l == 0) { sa[w] = a; sb[w] = b2; }
    __syncthreads();
    if (threadIdx.x < 8) {
        a = sa[threadIdx.x]; b2 = sb[threadIdx.x];
        #pragma unroll
        for (int o = 4; o > 0; o >>= 1) {
            a  += __shfl_down_sync(0xFFu, a, o);
            b2 += __shfl_down_sync(0xFFu, b2, o);
        }
        if (threadIdx.x == 0) { sa[0] = a; sb[0] = b2; }
    }
    __syncthreads();
    a = sa[0]; b2 = sb[0];
}

// ---------------- K0: build tokens/x_flat, add PE, LayerNorm1 ------------------
__global__ void __launch_bounds__(256) build_xwt_kernel(
    const float* __restrict__ x, const float* __restrict__ ctx,
    const float* __restrict__ regs,
    const float* __restrict__ gs, const float* __restrict__ gb)
{
    int row = blockIdx.x;           // 0..M_TOT-1
    int b = row / S, sIdx = row % S;
    int tid = threadIdx.x;

    float vals[3];
    float s = 0.f, s2 = 0.f;
    #pragma unroll
    for (int i = 0; i < 3; i++) {
        int k = tid + i * 256;
        float v;
        if (sIdx < G) {
            float base = (sIdx == 0) ? ctx[k] : regs[(sIdx - 1) * D + k];
            float expo = (float)(2 * (k / 2)) / (float)D;
            float denom = powf(10000.0f, expo);
            float angle = (float)sIdx / denom;
            float pe = (k & 1) ? cosf(angle) : sinf(angle);
            v = base + pe;
        } else {
            int pix = sIdx - G;
            v = x[((size_t)b * D + k) * HW + pix];
        }
        vals[i] = v;
        s += v; s2 += v * v;
    }
    block_reduce2(s, s2);
    float mean = s * (1.0f / D);
    float var  = s2 * (1.0f / D) - mean * mean;
    float rstd = rsqrtf(var + 1e-5f);
    #pragma unroll
    for (int i = 0; i < 3; i++) {
        int k = tid + i * 256;
        g_xwt[(size_t)row * D + k] = (vals[i] - mean) * rstd * gs[k] + gb[k];
    }
}

// ---------------- generic LN (for LN2) -----------------------------------------
__global__ void __launch_bounds__(256) ln_kernel(
    const float* __restrict__ in, const float* __restrict__ gs,
    const float* __restrict__ gb, float* __restrict__ out)
{
    int row = blockIdx.x;
    const float* p = in + (size_t)row * D;
    int tid = threadIdx.x;
    float vals[3];
    float s = 0.f, s2 = 0.f;
    #pragma unroll
    for (int i = 0; i < 3; i++) {
        float v = p[tid + i * 256];
        vals[i] = v; s += v; s2 += v * v;
    }
    block_reduce2(s, s2);
    float mean = s * (1.0f / D);
    float var  = s2 * (1.0f / D) - mean * mean;
    float rstd = rsqrtf(var + 1e-5f);
    #pragma unroll
    for (int i = 0; i < 3; i++) {
        int k = tid + i * 256;
        out[(size_t)row * D + k] = (vals[i] - mean) * rstd * gs[k] + gb[k];
    }
}

// ---------------- TF32 tensor-core GEMM: C = A[M,K] @ W[N,K]^T + bias ----------
// (+gelu)(+resid).  CTA tile 128x128, K-tile 32, 8 warps (2x4), warp tile 64x32.
// Smem stores tf32 bits, k-major, row stride 136 words (conflict-free frags).
#define KT 32
#define LDS_STRIDE 136

template<bool GELU, bool RESID>
__global__ void __launch_bounds__(256) gemm_tf32(
    const float* __restrict__ A, const float* __restrict__ W,
    const float* __restrict__ bias, const float* __restrict__ Rz,
    float* __restrict__ C, int Mm, int Nn, int Kk)
{
    __shared__ uint32_t As[KT * LDS_STRIDE];
    __shared__ uint32_t Bs[KT * LDS_STRIDE];

    int m0 = blockIdx.y * 128, n0 = blockIdx.x * 128;
    int tid = threadIdx.x;
    int warp = tid >> 5, lane = tid & 31;
    int g = lane >> 2, t = lane & 3;            // groupID, threadID-in-group
    int wm = warp >> 2, wn = warp & 3;          // warp tile: 64(m) x 32(n)

    float acc[4][4][4];
    #pragma unroll
    for (int i = 0; i < 4; i++)
        #pragma unroll
        for (int j = 0; j < 4; j++)
            #pragma unroll
            for (int c = 0; c < 4; c++) acc[i][j][c] = 0.f;

    int lrow = tid >> 1;                // 0..127  (tile row for loads)
    int lkb  = (tid & 1) * 16;          // k half

    for (int kt = 0; kt < Kk; kt += KT) {
        // ---- stage A and W tiles into smem (transposed to k-major, tf32) ----
        #pragma unroll
        for (int i = 0; i < 4; i++) {
            int kk = lkb + i * 4;
            float4 av = make_float4(0.f, 0.f, 0.f, 0.f);
            if (m0 + lrow < Mm)
                av = *(const float4*)&A[(size_t)(m0 + lrow) * Kk + kt + kk];
            As[(kk + 0) * LDS_STRIDE + lrow] = f2tf32(av.x);
            As[(kk + 1) * LDS_STRIDE + lrow] = f2tf32(av.y);
            As[(kk + 2) * LDS_STRIDE + lrow] = f2tf32(av.z);
            As[(kk + 3) * LDS_STRIDE + lrow] = f2tf32(av.w);
            float4 bv = *(const float4*)&W[(size_t)(n0 + lrow) * Kk + kt + kk];
            Bs[(kk + 0) * LDS_STRIDE + lrow] = f2tf32(bv.x);
            Bs[(kk + 1) * LDS_STRIDE + lrow] = f2tf32(bv.y);
            Bs[(kk + 2) * LDS_STRIDE + lrow] = f2tf32(bv.z);
            Bs[(kk + 3) * LDS_STRIDE + lrow] = f2tf32(bv.w);
        }
        __syncthreads();

        #pragma unroll
        for (int ks = 0; ks < KT; ks += 8) {
            uint32_t af[4][4], bf[4][2];
            #pragma unroll
            for (int mt = 0; mt < 4; mt++) {
                int m = wm * 64 + mt * 16 + g;
                af[mt][0] = As[(ks + t)     * LDS_STRIDE + m];
                af[mt][1] = As[(ks + t)     * LDS_STRIDE + m + 8];
                af[mt][2] = As[(ks + t + 4) * LDS_STRIDE + m];
                af[mt][3] = As[(ks + t + 4) * LDS_STRIDE + m + 8];
            }
            #pragma unroll
            for (int nt = 0; nt < 4; nt++) {
                int n = wn * 32 + nt * 8 + g;
                bf[nt][0] = Bs[(ks + t)     * LDS_STRIDE + n];
                bf[nt][1] = Bs[(ks + t + 4) * LDS_STRIDE + n];
            }
            #pragma unroll
            for (int mt = 0; mt < 4; mt++)
                #pragma unroll
                for (int nt = 0; nt < 4; nt++) {
                    asm volatile(
                        "mma.sync.aligned.m16n8k8.row.col.f32.tf32.tf32.f32 "
                        "{%0,%1,%2,%3}, {%4,%5,%6,%7}, {%8,%9}, {%0,%1,%2,%3};"
                        : "+f"(acc[mt][nt][0]), "+f"(acc[mt][nt][1]),
                          "+f"(acc[mt][nt][2]), "+f"(acc[mt][nt][3])
                        : "r"(af[mt][0]), "r"(af[mt][1]),
                          "r"(af[mt][2]), "r"(af[mt][3]),
                          "r"(bf[nt][0]), "r"(bf[nt][1]));
                }
        }
        __syncthreads();
    }

    // ---- epilogue ----
    #pragma unroll
    for (int mt = 0; mt < 4; mt++) {
        #pragma unroll
        for (int nt = 0; nt < 4; nt++) {
            #pragma unroll
            for (int c = 0; c < 4; c++) {
                int m = m0 + wm * 64 + mt * 16 + g + (c >> 1) * 8;
                int n = n0 + wn * 32 + nt * 8 + t * 2 + (c & 1);
                if (m >= Mm) continue;
                float v = acc[mt][nt][c] + bias[n];
                if (GELU) v = 0.5f * v * (1.0f + erff(v * 0.70710678118654752f));
                if (RESID) v += Rz[(size_t)m * Nn + n];
                C[(size_t)m * Nn + n] = v;
            }
        }
    }
}

// ---------------- fused flash attention (fp32, online softmax) -----------------
__global__ void __launch_bounds__(64) attn_kernel()
{
    int qt = blockIdx.x, h = blockIdx.y, b = blockIdx.z;
    int tid = threadIdx.x;
    int qi = qt * 64 + tid;
    bool active = qi < S;
    bool rowfeat = qi >= G;

    __shared__ float Ks[64][64];
    __shared__ float Vs[64][64];

    float q[DH];
    if (active) {
        const float* qp = g_qkv + ((size_t)b * S + qi) * (3 * D) + h * DH;
        #pragma unroll
        for (int d = 0; d < DH; d++) q[d] = qp[d];
    }
    float acc[DH];
    #pragma unroll
    for (int d = 0; d < DH; d++) acc[d] = 0.f;
    float m_i = -1e30f, l_i = 0.f;

    for (int k0 = 0; k0 < S; k0 += 64) {
        for (int i = 0; i < 64; i++) {
            int ki = k0 + i;
            float kv = 0.f, vv = 0.f;
            if (ki < S) {
                const float* base = g_qkv + ((size_t)b * S + ki) * (3 * D) + h * DH + tid;
                kv = base[D];
                vv = base[2 * D];
            }
            Ks[i][tid] = kv;
            Vs[i][tid] = vv;
        }
        __syncthreads();

        if (active) {
            #pragma unroll
            for (int c = 0; c < 4; c++) {
                float sc[16];
                float mx = m_i;
                #pragma unroll
                for (int jj = 0; jj < 16; jj++) {
                    int j = c * 16 + jj;
                    int ki = k0 + j;
                    float sv = 0.f;
                    #pragma unroll
                    for (int d = 0; d < DH; d++) sv += q[d] * Ks[j][d];
                    sv *= 0.125f;
                    if (ki >= S || (rowfeat && ki < G)) sv = -1e30f;
                    sc[jj] = sv;
                    mx = fmaxf(mx, sv);
                }
                float scale = __expf(m_i - mx);
                l_i *= scale;
                #pragma unroll
                for (int d = 0; d < DH; d++) acc[d] *= scale;
                #pragma unroll
                for (int jj = 0; jj < 16; jj++) {
                    int j = c * 16 + jj;
                    float p = __expf(sc[jj] - mx);
                    l_i += p;
                    #pragma unroll
                    for (int d = 0; d < DH; d++) acc[d] += p * Vs[j][d];
                }
                m_i = mx;
            }
        }
        __syncthreads();
    }

    if (active) {
        float inv = 1.0f / l_i;
        float* op = g_o + ((size_t)b * S + qi) * D + h * DH;
        #pragma unroll
        for (int d = 0; d < DH; d++) op[d] = acc[d] * inv;
    }
}

// ---------------- scatter final outputs ----------------------------------------
__global__ void __launch_bounds__(256) scatter_out_kernel(float* __restrict__ out)
{
    int idx = blockIdx.x * 256 + threadIdx.x;
    const int FEAT = BB * D * HW;
    const int CTX  = BB * D;
    const int REG  = BB * 4 * D;
    if (idx < FEAT) {
        int b = idx / (D * HW);
        int r = idx % (D * HW);
        int k = r / HW;
        int pix = r % HW;
        out[idx] = g_y2[((size_t)(b * S + G + pix)) * D + k];
    } else if (idx < FEAT + CTX) {
        int i2 = idx - FEAT;
        int b = i2 / D, k = i2 % D;
        out[idx] = g_y2[((size_t)(b * S)) * D + k];
    } else if (idx < FEAT + CTX + REG) {
        int i3 = idx - FEAT - CTX;
        int b = i3 / (4 * D);
        int rr = (i3 / D) % 4;
        int k = i3 % D;
        out[idx] = g_y2[((size_t)(b * S + 1 + rr)) * D + k];
    }
}

// ---------------- host launcher -------------------------------------------------
extern "C" void kernel_launch(void* const* d_in, const int* in_sizes, int n_in,
                              void* d_out, int out_size)
{
    const float* x    = (const float*)d_in[0];
    const float* ctx  = (const float*)d_in[1];
    const float* regs = (const float*)d_in[2];
    const float* wqkv = (const float*)d_in[3];
    const float* bqkv = (const float*)d_in[4];
    const float* wout = (const float*)d_in[5];
    const float* bout = (const float*)d_in[6];
    const float* ln1s = (const float*)d_in[7];
    const float* ln1b = (const float*)d_in[8];
    const float* ln2s = (const float*)d_in[9];
    const float* ln2b = (const float*)d_in[10];
    const float* w1   = (const float*)d_in[11];
    const float* b1   = (const float*)d_in[12];
    const float* w2   = (const float*)d_in[13];
    const float* b2   = (const float*)d_in[14];
    float* out = (float*)d_out;
    (void)in_sizes; (void)n_in; (void)out_size;

    float *xwt, *qkv, *o, *y, *z, *hbuf, *y2;
    cudaGetSymbolAddress((void**)&xwt,  g_xwt);
    cudaGetSymbolAddress((void**)&qkv,  g_qkv);
    cudaGetSymbolAddress((void**)&o,    g_o);
    cudaGetSymbolAddress((void**)&y,    g_y);
    cudaGetSymbolAddress((void**)&z,    g_z);
    cudaGetSymbolAddress((void**)&hbuf, g_h);
    cudaGetSymbolAddress((void**)&y2,   g_y2);

    const int M = M_TOT;
    const int MG = (M + 127) / 128;            // 65

    build_xwt_kernel<<<M, 256>>>(x, ctx, regs, ln1s, ln1b);

    gemm_tf32<false, false><<<dim3(3 * D / 128, MG), 256>>>(
        xwt, wqkv, bqkv, nullptr, qkv, M, 3 * D, D);

    attn_kernel<<<dim3((S + 63) / 64, NH, BB), 64>>>();

    gemm_tf32<false, true><<<dim3(D / 128, MG), 256>>>(
        o, wout, bout, xwt, y, M, D, D);

    ln_kernel<<<M, 256>>>(y, ln2s, ln2b, z);

    gemm_tf32<true, false><<<dim3(4 * D / 128, MG), 256>>>(
        z, w1, b1, nullptr, hbuf, M, 4 * D, D);

    gemm_tf32<false, true><<<dim3(D / 128, MG), 256>>>(
        hbuf, w2, b2, y, y2, M, D, 4 * D);

    const int TOT = BB * D * HW + BB * D + BB * 4 * D;
    scatter_out_kernel<<<(TOT + 255) / 256, 256>>>(out);
}

// round 3
// speedup vs baseline: 3.2580x; 2.1217x over previous
#include <cuda_runtime.h>
#include <math.h>
#include <stdint.h>

#define BB 8
#define D 768
#define NH 12
#define DH 64
#define HW 1024
#define G 5
#define S 1029           // G + HW
#define M_TOT (BB * S)   // 8232

// ---------------- scratch (static device globals; no runtime allocs) ----------
__device__ float g_xwt[(size_t)M_TOT * D];
__device__ float g_qkv[(size_t)M_TOT * 3 * D];
__device__ float g_o  [(size_t)M_TOT * D];
__device__ float g_y  [(size_t)M_TOT * D];
__device__ float g_z  [(size_t)M_TOT * D];
__device__ float g_h  [(size_t)M_TOT * 4 * D];
__device__ float g_y2 [(size_t)M_TOT * D];

__device__ __forceinline__ uint32_t f2tf32(float x) {
    uint32_t r;
    asm("cvt.rna.tf32.f32 %0, %1;" : "=r"(r) : "f"(x));
    return r;
}

__device__ __forceinline__ void cp_async16(uint32_t dst_smem, const void* src, int src_bytes) {
    asm volatile("cp.async.cg.shared.global [%0], [%1], 16, %2;"
                 :: "r"(dst_smem), "l"(src), "r"(src_bytes));
}
__device__ __forceinline__ void cp_commit() { asm volatile("cp.async.commit_group;"); }
template<int N>
__device__ __forceinline__ void cp_wait() { asm volatile("cp.async.wait_group %0;" :: "n"(N)); }

__device__ __forceinline__ void mma_tf32(float* c, const uint32_t* a, const uint32_t* b) {
    asm volatile(
        "mma.sync.aligned.m16n8k8.row.col.f32.tf32.tf32.f32 "
        "{%0,%1,%2,%3}, {%4,%5,%6,%7}, {%8,%9}, {%0,%1,%2,%3};"
        : "+f"(c[0]), "+f"(c[1]), "+f"(c[2]), "+f"(c[3])
        : "r"(a[0]), "r"(a[1]), "r"(a[2]), "r"(a[3]), "r"(b[0]), "r"(b[1]));
}

// ---------------- block reduce (sum, sumsq) over 256 threads -------------------
__device__ __forceinline__ void block_reduce2(float& a, float& b2) {
    #pragma unroll
    for (int o = 16; o > 0; o >>= 1) {
        a  += __shfl_down_sync(0xFFFFFFFFu, a, o);
        b2 += __shfl_down_sync(0xFFFFFFFFu, b2, o);
    }
    __shared__ float sa[8], sb[8];
    int w = threadIdx.x >> 5, l = threadIdx.x & 31;
    if (l == 0) { sa[w] = a; sb[w] = b2; }
    __syncthreads();
    if (threadIdx.x < 8) {
        a = sa[threadIdx.x]; b2 = sb[threadIdx.x];
        #pragma unroll
        for (int o = 4; o > 0; o >>= 1) {
            a  += __shfl_down_sync(0xFFu, a, o);
            b2 += __shfl_down_sync(0xFFu, b2, o);
        }
        if (threadIdx.x == 0) { sa[0] = a; sb[0] = b2; }
    }
    __syncthreads();
    a = sa[0]; b2 = sb[0];
}

// ---------------- K0: build tokens/x_flat, add PE, LayerNorm1 ------------------
__global__ void __launch_bounds__(256) build_xwt_kernel(
    const float* __restrict__ x, const float* __restrict__ ctx,
    const float* __restrict__ regs,
    const float* __restrict__ gs, const float* __restrict__ gb)
{
    int row = blockIdx.x;
    int b = row / S, sIdx = row % S;
    int tid = threadIdx.x;

    float vals[3];
    float s = 0.f, s2 = 0.f;
    #pragma unroll
    for (int i = 0; i < 3; i++) {
        int k = tid + i * 256;
        float v;
        if (sIdx < G) {
            float base = (sIdx == 0) ? ctx[k] : regs[(sIdx - 1) * D + k];
            float expo = (float)(2 * (k / 2)) / (float)D;
            float denom = powf(10000.0f, expo);
            float angle = (float)sIdx / denom;
            float pe = (k & 1) ? cosf(angle) : sinf(angle);
            v = base + pe;
        } else {
            int pix = sIdx - G;
            v = x[((size_t)b * D + k) * HW + pix];
        }
        vals[i] = v;
        s += v; s2 += v * v;
    }
    block_reduce2(s, s2);
    float mean = s * (1.0f / D);
    float var  = s2 * (1.0f / D) - mean * mean;
    float rstd = rsqrtf(var + 1e-5f);
    #pragma unroll
    for (int i = 0; i < 3; i++) {
        int k = tid + i * 256;
        g_xwt[(size_t)row * D + k] = (vals[i] - mean) * rstd * gs[k] + gb[k];
    }
}

// ---------------- generic LN (for LN2) -----------------------------------------
__global__ void __launch_bounds__(256) ln_kernel(
    const float* __restrict__ in, const float* __restrict__ gs,
    const float* __restrict__ gb, float* __restrict__ out)
{
    int row = blockIdx.x;
    const float* p = in + (size_t)row * D;
    int tid = threadIdx.x;
    float vals[3];
    float s = 0.f, s2 = 0.f;
    #pragma unroll
    for (int i = 0; i < 3; i++) {
        float v = p[tid + i * 256];
        vals[i] = v; s += v; s2 += v * v;
    }
    block_reduce2(s, s2);
    float mean = s * (1.0f / D);
    float var  = s2 * (1.0f / D) - mean * mean;
    float rstd = rsqrtf(var + 1e-5f);
    #pragma unroll
    for (int i = 0; i < 3; i++) {
        int k = tid + i * 256;
        out[(size_t)row * D + k] = (vals[i] - mean) * rstd * gs[k] + gb[k];
    }
}

// ---------------- TF32 tensor-core GEMM, cp.async double-buffered --------------
// C = A[M,K] @ W[N,K]^T + bias (+gelu)(+resid)
// CTA tile 128x128, K-tile 32, 8 warps (2x4), warp tile 64x32.
// Smem: raw fp32 bits, row-major [row][k], stride 36 words (conflict-free frags).
#define KT 32
#define AST 36
#define GEMM_SMEM (4 * 128 * AST * 4)   // 2 stages x (A,B) x 128x36 words

template<bool GELU, bool RESID>
__global__ void __launch_bounds__(256) gemm_tf32(
    const float* __restrict__ A, const float* __restrict__ W,
    const float* __restrict__ bias, const float* __restrict__ Rz,
    float* __restrict__ C, int Mm, int Nn, int Kk)
{
    extern __shared__ float smf[];
    const int BUF = 128 * AST;

    int m0 = blockIdx.y * 128, n0 = blockIdx.x * 128;
    int tid = threadIdx.x;
    int warp = tid >> 5, lane = tid & 31;
    int g = lane >> 2, t = lane & 3;
    int wm = warp >> 2, wn = warp & 3;

    float acc[4][4][4];
    #pragma unroll
    for (int i = 0; i < 4; i++)
        #pragma unroll
        for (int j = 0; j < 4; j++)
            #pragma unroll
            for (int c = 0; c < 4; c++) acc[i][j][c] = 0.f;

    int lm = tid >> 1;                 // 0..127
    int lc = (tid & 1) * 4;            // chunk base (k = 4*chunk), chunks 0..7

    uint32_t smem_base = (uint32_t)__cvta_generic_to_shared(smf);

    const int ntiles = Kk / KT;

    // ---- stage loader: 8 cp.async per thread ----
    auto load_stage = [&](int it, int stage) {
        int kt = it * KT;
        #pragma unroll
        for (int i = 0; i < 4; i++) {
            int c = lc + ((i & 1) ? 16 : 0) + ((i >> 1) ? 8 : 0); // k offsets 0,16,8,24 -> covers 0..28 step4 w/ lc
            // A
            {
                uint32_t dst = smem_base + (stage * BUF + lm * AST + c) * 4;
                const void* src = &A[(size_t)(m0 + lm) * Kk + kt + c];
                cp_async16(dst, src, (m0 + lm < Mm) ? 16 : 0);
            }
            // B (W rows always in range: Nn multiple of 128)
            {
                uint32_t dst = smem_base + ((2 + stage) * BUF + lm * AST + c) * 4;
                const void* src = &W[(size_t)(n0 + lm) * Kk + kt + c];
                cp_async16(dst, src, 16);
            }
        }
        cp_commit();
    };

    load_stage(0, 0);

    for (int it = 0; it < ntiles; it++) {
        if (it + 1 < ntiles) {
            load_stage(it + 1, (it + 1) & 1);
            cp_wait<1>();
        } else {
            cp_wait<0>();
        }
        __syncthreads();

        const float* Ab = smf + (it & 1) * BUF;
        const float* Bb = smf + (2 + (it & 1)) * BUF;

        #pragma unroll
        for (int ks = 0; ks < KT; ks += 8) {
            uint32_t af[4][4], bf[4][2];
            #pragma unroll
            for (int mt = 0; mt < 4; mt++) {
                int m = wm * 64 + mt * 16 + g;
                af[mt][0] = f2tf32(Ab[m * AST + ks + t]);
                af[mt][1] = f2tf32(Ab[(m + 8) * AST + ks + t]);
                af[mt][2] = f2tf32(Ab[m * AST + ks + t + 4]);
                af[mt][3] = f2tf32(Ab[(m + 8) * AST + ks + t + 4]);
            }
            #pragma unroll
            for (int nt = 0; nt < 4; nt++) {
                int n = wn * 32 + nt * 8 + g;
                bf[nt][0] = f2tf32(Bb[n * AST + ks + t]);
                bf[nt][1] = f2tf32(Bb[n * AST + ks + t + 4]);
            }
            #pragma unroll
            for (int mt = 0; mt < 4; mt++)
                #pragma unroll
                for (int nt = 0; nt < 4; nt++)
                    mma_tf32(acc[mt][nt], af[mt], bf[nt]);
        }
        __syncthreads();
    }

    // ---- epilogue ----
    #pragma unroll
    for (int mt = 0; mt < 4; mt++) {
        #pragma unroll
        for (int nt = 0; nt < 4; nt++) {
            #pragma unroll
            for (int c = 0; c < 4; c++) {
                int m = m0 + wm * 64 + mt * 16 + g + (c >> 1) * 8;
                int n = n0 + wn * 32 + nt * 8 + t * 2 + (c & 1);
                if (m >= Mm) continue;
                float v = acc[mt][nt][c] + bias[n];
                if (GELU) v = 0.5f * v * (1.0f + erff(v * 0.70710678118654752f));
                if (RESID) v += Rz[(size_t)m * Nn + n];
                C[(size_t)m * Nn + n] = v;
            }
        }
    }
}

// ---------------- tensor-core flash attention (tf32 mma, online softmax) -------
// Block: 128 threads (4 warps). Each block: 64 q-rows for one (b,h).
// Warp w handles q rows [w*16, w*16+16). K-tile = 64 keys.
#define KST 68                       // smem row stride (words) for K/V/P tiles
#define ATTN_SMEM (3 * 64 * KST * 4)

__global__ void __launch_bounds__(128) attn_mma_kernel()
{
    extern __shared__ float asm_[];
    float* Ks = asm_;
    float* Vs = asm_ + 64 * KST;
    float* Ps = asm_ + 2 * 64 * KST;

    int qt = blockIdx.x, h = blockIdx.y, b = blockIdx.z;
    int tid = threadIdx.x;
    int warp = tid >> 5, lane = tid & 31;
    int g = lane >> 2, t = lane & 3;

    int row0 = qt * 64 + warp * 16 + g;   // global q index (row0, row0+8)
    int row1 = row0 + 8;
    bool v0 = row0 < S, v1 = row1 < S;

    // ---- Q fragments straight from global (scaled by 1/sqrt(dh)) ----
    uint32_t qf[8][4];
    {
        const float* q0 = g_qkv + ((size_t)(b * S) + (v0 ? row0 : 0)) * (3 * D) + h * DH;
        const float* q1 = g_qkv + ((size_t)(b * S) + (v1 ? row1 : 0)) * (3 * D) + h * DH;
        #pragma unroll
        for (int ks = 0; ks < 8; ks++) {
            int k0 = ks * 8 + t;
            qf[ks][0] = f2tf32(v0 ? q0[k0] * 0.125f : 0.f);
            qf[ks][1] = f2tf32(v1 ? q1[k0] * 0.125f : 0.f);
            qf[ks][2] = f2tf32(v0 ? q0[k0 + 4] * 0.125f : 0.f);
            qf[ks][3] = f2tf32(v1 ? q1[k0 + 4] * 0.125f : 0.f);
        }
    }

    float oacc[8][4];
    #pragma unroll
    for (int i = 0; i < 8; i++)
        #pragma unroll
        for (int c = 0; c < 4; c++) oacc[i][c] = 0.f;
    float m0r = -1e30f, m1r = -1e30f, l0 = 0.f, l1 = 0.f;

    const int NT = (S + 63) / 64;    // 17 key tiles

    for (int kt = 0; kt < NT; kt++) {
        // ---- load K/V tile (64 keys x 64 dims), float4, zero-padded ----
        #pragma unroll
        for (int i = 0; i < 8; i++) {
            int idx = tid + i * 128;         // 0..1023
            int r = idx >> 4, c4 = (idx & 15) * 4;
            int ki = kt * 64 + r;
            float4 kv = make_float4(0.f, 0.f, 0.f, 0.f);
            float4 vv = make_float4(0.f, 0.f, 0.f, 0.f);
            if (ki < S) {
                const float* base = g_qkv + ((size_t)(b * S) + ki) * (3 * D) + h * DH + c4;
                kv = *(const float4*)(base + D);
                vv = *(const float4*)(base + 2 * D);
            }
            *(float4*)&Ks[r * KST + c4] = kv;
            *(float4*)&Vs[r * KST + c4] = vv;
        }
        __syncthreads();

        // ---- scores S = Q @ K^T ----
        float sacc[8][4];
        #pragma unroll
        for (int nt = 0; nt < 8; nt++) {
            #pragma unroll
            for (int c = 0; c < 4; c++) sacc[nt][c] = 0.f;
            #pragma unroll
            for (int ks = 0; ks < 8; ks++) {
                uint32_t bf[2];
                bf[0] = f2tf32(Ks[(nt * 8 + g) * KST + ks * 8 + t]);
                bf[1] = f2tf32(Ks[(nt * 8 + g) * KST + ks * 8 + t + 4]);
                mma_tf32(sacc[nt], qf[ks], bf);
            }
        }

        // ---- mask + online softmax ----
        bool feat0 = row0 >= G, feat1 = row1 >= G;
        float mx0 = -1e30f, mx1 = -1e30f;
        #pragma unroll
        for (int nt = 0; nt < 8; nt++) {
            #pragma unroll
            for (int c = 0; c < 4; c++) {
                int col = kt * 64 + nt * 8 + 2 * t + (c & 1);
                bool bad = (col >= S) || ((c < 2 ? feat0 : feat1) && col < G);
                if (bad) sacc[nt][c] = -1e30f;
            }
            mx0 = fmaxf(mx0, fmaxf(sacc[nt][0], sacc[nt][1]));
            mx1 = fmaxf(mx1, fmaxf(sacc[nt][2], sacc[nt][3]));
        }
        mx0 = fmaxf(mx0, __shfl_xor_sync(0xFFFFFFFFu, mx0, 1));
        mx0 = fmaxf(mx0, __shfl_xor_sync(0xFFFFFFFFu, mx0, 2));
        mx1 = fmaxf(mx1, __shfl_xor_sync(0xFFFFFFFFu, mx1, 1));
        mx1 = fmaxf(mx1, __shfl_xor_sync(0xFFFFFFFFu, mx1, 2));

        float mn0 = fmaxf(m0r, mx0), mn1 = fmaxf(m1r, mx1);
        float sc0 = __expf(m0r - mn0), sc1 = __expf(m1r - mn1);
        m0r = mn0; m1r = mn1;

        float ls0 = 0.f, ls1 = 0.f;
        int prow0 = (warp * 16 + g) * KST;
        int prow1 = (warp * 16 + g + 8) * KST;
        #pragma unroll
        for (int nt = 0; nt < 8; nt++) {
            float p0 = __expf(sacc[nt][0] - mn0);
            float p1 = __expf(sacc[nt][1] - mn0);
            float p2 = __expf(sacc[nt][2] - mn1);
            float p3 = __expf(sacc[nt][3] - mn1);
            ls0 += p0 + p1; ls1 += p2 + p3;
            Ps[prow0 + nt * 8 + 2 * t]     = p0;
            Ps[prow0 + nt * 8 + 2 * t + 1] = p1;
            Ps[prow1 + nt * 8 + 2 * t]     = p2;
            Ps[prow1 + nt * 8 + 2 * t + 1] = p3;
            #pragma unroll
            for (int c = 0; c < 4; c++)
                oacc[nt][c] *= (c < 2) ? sc0 : sc1;
        }
        ls0 += __shfl_xor_sync(0xFFFFFFFFu, ls0, 1);
        ls0 += __shfl_xor_sync(0xFFFFFFFFu, ls0, 2);
        ls1 += __shfl_xor_sync(0xFFFFFFFFu, ls1, 1);
        ls1 += __shfl_xor_sync(0xFFFFFFFFu, ls1, 2);
        l0 = l0 * sc0 + ls0;
        l1 = l1 * sc1 + ls1;
        __syncwarp();

        // ---- O += P @ V ----
        #pragma unroll
        for (int ks = 0; ks < 8; ks++) {
            uint32_t pf[4];
            pf[0] = f2tf32(Ps[prow0 + ks * 8 + t]);
            pf[1] = f2tf32(Ps[prow1 + ks * 8 + t]);
            pf[2] = f2tf32(Ps[prow0 + ks * 8 + t + 4]);
            pf[3] = f2tf32(Ps[prow1 + ks * 8 + t + 4]);
            #pragma unroll
            for (int nt = 0; nt < 8; nt++) {
                uint32_t vf[2];
                vf[0] = f2tf32(Vs[(ks * 8 + t) * KST + nt * 8 + g]);
                vf[1] = f2tf32(Vs[(ks * 8 + t + 4) * KST + nt * 8 + g]);
                mma_tf32(oacc[nt], pf, vf);
            }
        }
        __syncthreads();
    }

    // ---- write O ----
    float inv0 = 1.0f / l0, inv1 = 1.0f / l1;
    float* o0 = g_o + ((size_t)(b * S) + row0) * D + h * DH;
    float* o1 = g_o + ((size_t)(b * S) + row1) * D + h * DH;
    #pragma unroll
    for (int nt = 0; nt < 8; nt++) {
        int cbase = nt * 8 + 2 * t;
        if (v0) {
            o0[cbase]     = oacc[nt][0] * inv0;
            o0[cbase + 1] = oacc[nt][1] * inv0;
        }
        if (v1) {
            o1[cbase]     = oacc[nt][2] * inv1;
            o1[cbase + 1] = oacc[nt][3] * inv1;
        }
    }
}

// ---------------- scatter final outputs ----------------------------------------
__global__ void __launch_bounds__(256) scatter_out_kernel(float* __restrict__ out)
{
    int idx = blockIdx.x * 256 + threadIdx.x;
    const int FEAT = BB * D * HW;
    const int CTX  = BB * D;
    const int REG  = BB * 4 * D;
    if (idx < FEAT) {
        int b = idx / (D * HW);
        int r = idx % (D * HW);
        int k = r / HW;
        int pix = r % HW;
        out[idx] = g_y2[((size_t)(b * S + G + pix)) * D + k];
    } else if (idx < FEAT + CTX) {
        int i2 = idx - FEAT;
        int b = i2 / D, k = i2 % D;
        out[idx] = g_y2[((size_t)(b * S)) * D + k];
    } else if (idx < FEAT + CTX + REG) {
        int i3 = idx - FEAT - CTX;
        int b = i3 / (4 * D);
        int rr = (i3 / D) % 4;
        int k = i3 % D;
        out[idx] = g_y2[((size_t)(b * S + 1 + rr)) * D + k];
    }
}

// ---------------- host launcher -------------------------------------------------
extern "C" void kernel_launch(void* const* d_in, const int* in_sizes, int n_in,
                              void* d_out, int out_size)
{
    const float* x    = (const float*)d_in[0];
    const float* ctx  = (const float*)d_in[1];
    const float* regs = (const float*)d_in[2];
    const float* wqkv = (const float*)d_in[3];
    const float* bqkv = (const float*)d_in[4];
    const float* wout = (const float*)d_in[5];
    const float* bout = (const float*)d_in[6];
    const float* ln1s = (const float*)d_in[7];
    const float* ln1b = (const float*)d_in[8];
    const float* ln2s = (const float*)d_in[9];
    const float* ln2b = (const float*)d_in[10];
    const float* w1   = (const float*)d_in[11];
    const float* b1   = (const float*)d_in[12];
    const float* w2   = (const float*)d_in[13];
    const float* b2   = (const float*)d_in[14];
    float* out = (float*)d_out;
    (void)in_sizes; (void)n_in; (void)out_size;

    float *xwt, *qkv, *o, *y, *z, *hbuf, *y2;
    cudaGetSymbolAddress((void**)&xwt,  g_xwt);
    cudaGetSymbolAddress((void**)&qkv,  g_qkv);
    cudaGetSymbolAddress((void**)&o,    g_o);
    cudaGetSymbolAddress((void**)&y,    g_y);
    cudaGetSymbolAddress((void**)&z,    g_z);
    cudaGetSymbolAddress((void**)&hbuf, g_h);
    cudaGetSymbolAddress((void**)&y2,   g_y2);

    cudaFuncSetAttribute(gemm_tf32<false, false>,
        cudaFuncAttributeMaxDynamicSharedMemorySize, GEMM_SMEM);
    cudaFuncSetAttribute(gemm_tf32<false, true>,
        cudaFuncAttributeMaxDynamicSharedMemorySize, GEMM_SMEM);
    cudaFuncSetAttribute(gemm_tf32<true, false>,
        cudaFuncAttributeMaxDynamicSharedMemorySize, GEMM_SMEM);
    cudaFuncSetAttribute(attn_mma_kernel,
        cudaFuncAttributeMaxDynamicSharedMemorySize, ATTN_SMEM);

    const int M = M_TOT;
    const int MG = (M + 127) / 128;            // 65

    build_xwt_kernel<<<M, 256>>>(x, ctx, regs, ln1s, ln1b);

    gemm_tf32<false, false><<<dim3(3 * D / 128, MG), 256, GEMM_SMEM>>>(
        xwt, wqkv, bqkv, nullptr, qkv, M, 3 * D, D);

    attn_mma_kernel<<<dim3((S + 63) / 64, NH, BB), 128, ATTN_SMEM>>>();

    gemm_tf32<false, true><<<dim3(D / 128, MG), 256, GEMM_SMEM>>>(
        o, wout, bout, xwt, y, M, D, D);

    ln_kernel<<<M, 256>>>(y, ln2s, ln2b, z);

    gemm_tf32<true, false><<<dim3(4 * D / 128, MG), 256, GEMM_SMEM>>>(
        z, w1, b1, nullptr, hbuf, M, 4 * D, D);

    gemm_tf32<false, true><<<dim3(D / 128, MG), 256, GEMM_SMEM>>>(
        hbuf, w2, b2, y, y2, M, D, 4 * D);

    const int TOT = BB * D * HW + BB * D + BB * 4 * D;
    scatter_out_kernel<<<(TOT + 255) / 256, 256>>>(out);
}

// round 4
// speedup vs baseline: 3.6763x; 1.1284x over previous
#include <cuda_runtime.h>
#include <math.h>
#include <stdint.h>

#define BB 8
#define D 768
#define NH 12
#define DH 64
#define HW 1024
#define G 5
#define S 1029           // G + HW
#define M_TOT (BB * S)   // 8232

// ---------------- scratch (static device globals; no runtime allocs) ----------
__device__ float    g_xwt  [(size_t)M_TOT * D];        // LN1 out fp32 (residual)
__device__ uint32_t g_xwt32[(size_t)M_TOT * D];        // LN1 out tf32 bits
__device__ uint32_t g_qkv  [(size_t)M_TOT * 3 * D];    // QKV tf32 bits
__device__ uint32_t g_o    [(size_t)M_TOT * D];        // attn out tf32 bits
__device__ float    g_y    [(size_t)M_TOT * D];        // out_proj + resid fp32
__device__ uint32_t g_z32  [(size_t)M_TOT * D];        // LN2 out tf32 bits
__device__ uint32_t g_h32  [(size_t)M_TOT * 4 * D];    // gelu out tf32 bits
__device__ float    g_y2   [(size_t)M_TOT * D];        // final fp32

// tf32 weights (converted once per launch)
__device__ uint32_t g_wqkv32[3 * D * D];
__device__ uint32_t g_wout32[D * D];
__device__ uint32_t g_w132  [4 * D * D];
__device__ uint32_t g_w232  [4 * D * D];

__device__ __forceinline__ uint32_t f2tf32(float x) {
    uint32_t r;
    asm("cvt.rna.tf32.f32 %0, %1;" : "=r"(r) : "f"(x));
    return r;
}

__device__ __forceinline__ void cp_async16(uint32_t dst_smem, const void* src, int src_bytes) {
    asm volatile("cp.async.cg.shared.global [%0], [%1], 16, %2;"
                 :: "r"(dst_smem), "l"(src), "r"(src_bytes));
}
__device__ __forceinline__ void cp_commit() { asm volatile("cp.async.commit_group;"); }
template<int N>
__device__ __forceinline__ void cp_wait() { asm volatile("cp.async.wait_group %0;" :: "n"(N)); }

__device__ __forceinline__ void mma_tf32(float* c, const uint32_t* a, const uint32_t* b) {
    asm volatile(
        "mma.sync.aligned.m16n8k8.row.col.f32.tf32.tf32.f32 "
        "{%0,%1,%2,%3}, {%4,%5,%6,%7}, {%8,%9}, {%0,%1,%2,%3};"
        : "+f"(c[0]), "+f"(c[1]), "+f"(c[2]), "+f"(c[3])
        : "r"(a[0]), "r"(a[1]), "r"(a[2]), "r"(a[3]), "r"(b[0]), "r"(b[1]));
}

// ---------------- weight conversion (once per launch) ---------------------------
__global__ void __launch_bounds__(256) convert_weights_kernel(
    const float* __restrict__ wqkv, const float* __restrict__ wout,
    const float* __restrict__ w1, const float* __restrict__ w2)
{
    int i = blockIdx.x * 256 + threadIdx.x;
    if (i < 3 * D * D) g_wqkv32[i] = f2tf32(wqkv[i]);
    if (i < D * D)     g_wout32[i] = f2tf32(wout[i]);
    if (i < 4 * D * D) {
        g_w132[i] = f2tf32(w1[i]);
        g_w232[i] = f2tf32(w2[i]);
    }
}

// ---------------- block reduce (sum, sumsq) over 256 threads -------------------
__device__ __forceinline__ void block_reduce2(float& a, float& b2) {
    #pragma unroll
    for (int o = 16; o > 0; o >>= 1) {
        a  += __shfl_down_sync(0xFFFFFFFFu, a, o);
        b2 += __shfl_down_sync(0xFFFFFFFFu, b2, o);
    }
    __shared__ float sa[8], sb[8];
    int w = threadIdx.x >> 5, l = threadIdx.x & 31;
    if (l == 0) { sa[w] = a; sb[w] = b2; }
    __syncthreads();
    if (threadIdx.x < 8) {
        a = sa[threadIdx.x]; b2 = sb[threadIdx.x];
        #pragma unroll
        for (int o = 4; o > 0; o >>= 1) {
            a  += __shfl_down_sync(0xFFu, a, o);
            b2 += __shfl_down_sync(0xFFu, b2, o);
        }
        if (threadIdx.x == 0) { sa[0] = a; sb[0] = b2; }
    }
    __syncthreads();
    a = sa[0]; b2 = sb[0];
}

// ---------------- K0: build tokens/x_flat, add PE, LayerNorm1 ------------------
__global__ void __launch_bounds__(256) build_xwt_kernel(
    const float* __restrict__ x, const float* __restrict__ ctx,
    const float* __restrict__ regs,
    const float* __restrict__ gs, const float* __restrict__ gb)
{
    int row = blockIdx.x;
    int b = row / S, sIdx = row % S;
    int tid = threadIdx.x;

    float vals[3];
    float s = 0.f, s2 = 0.f;
    #pragma unroll
    for (int i = 0; i < 3; i++) {
        int k = tid + i * 256;
        float v;
        if (sIdx < G) {
            float base = (sIdx == 0) ? ctx[k] : regs[(sIdx - 1) * D + k];
            float expo = (float)(2 * (k / 2)) / (float)D;
            float denom = powf(10000.0f, expo);
            float angle = (float)sIdx / denom;
            float pe = (k & 1) ? cosf(angle) : sinf(angle);
            v = base + pe;
        } else {
            int pix = sIdx - G;
            v = x[((size_t)b * D + k) * HW + pix];
        }
        vals[i] = v;
        s += v; s2 += v * v;
    }
    block_reduce2(s, s2);
    float mean = s * (1.0f / D);
    float var  = s2 * (1.0f / D) - mean * mean;
    float rstd = rsqrtf(var + 1e-5f);
    #pragma unroll
    for (int i = 0; i < 3; i++) {
        int k = tid + i * 256;
        float v = (vals[i] - mean) * rstd * gs[k] + gb[k];
        g_xwt  [(size_t)row * D + k] = v;
        g_xwt32[(size_t)row * D + k] = f2tf32(v);
    }
}

// ---------------- LN2 (writes tf32 bits) ----------------------------------------
__global__ void __launch_bounds__(256) ln_kernel(
    const float* __restrict__ in, const float* __restrict__ gs,
    const float* __restrict__ gb, uint32_t* __restrict__ out)
{
    int row = blockIdx.x;
    const float* p = in + (size_t)row * D;
    int tid = threadIdx.x;
    float vals[3];
    float s = 0.f, s2 = 0.f;
    #pragma unroll
    for (int i = 0; i < 3; i++) {
        float v = p[tid + i * 256];
        vals[i] = v; s += v; s2 += v * v;
    }
    block_reduce2(s, s2);
    float mean = s * (1.0f / D);
    float var  = s2 * (1.0f / D) - mean * mean;
    float rstd = rsqrtf(var + 1e-5f);
    #pragma unroll
    for (int i = 0; i < 3; i++) {
        int k = tid + i * 256;
        out[(size_t)row * D + k] = f2tf32((vals[i] - mean) * rstd * gs[k] + gb[k]);
    }
}

// ---------------- TF32 tensor-core GEMM, 3-stage cp.async, all-bits ------------
// C = A[M,K] @ W[N,K]^T + bias (+gelu)(+resid), A/W are tf32 bits.
// CTA tile 128x128, K-tile 32, 8 warps (2x4), warp tile 64x32.
#define KT 32
#define AST 36
#define GEMM_SMEM (3 * 2 * 128 * AST * 4)   // 3 stages x (A,B) x 128x36 words

template<bool GELU, bool RESID, bool OUT32>
__global__ void __launch_bounds__(256, 2) gemm_tf32(
    const uint32_t* __restrict__ A, const uint32_t* __restrict__ W,
    const float* __restrict__ bias, const float* __restrict__ Rz,
    float* __restrict__ C, int Mm, int Nn, int Kk)
{
    extern __shared__ uint32_t smu[];
    const int BUF = 128 * AST;

    int m0 = blockIdx.y * 128, n0 = blockIdx.x * 128;
    int tid = threadIdx.x;
    int warp = tid >> 5, lane = tid & 31;
    int g = lane >> 2, t = lane & 3;
    int wm = warp >> 2, wn = warp & 3;

    float acc[4][4][4];
    #pragma unroll
    for (int i = 0; i < 4; i++)
        #pragma unroll
        for (int j = 0; j < 4; j++)
            #pragma unroll
            for (int c = 0; c < 4; c++) acc[i][j][c] = 0.f;

    int lm = tid >> 1;
    int lc = (tid & 1) * 4;

    uint32_t smem_base = (uint32_t)__cvta_generic_to_shared(smu);
    const int ntiles = Kk / KT;

    auto load_stage = [&](int it, int stage) {
        int kt = it * KT;
        #pragma unroll
        for (int i = 0; i < 4; i++) {
            int c = lc + ((i & 1) ? 16 : 0) + ((i >> 1) ? 8 : 0);
            uint32_t dstA = smem_base + (stage * 2 * BUF + lm * AST + c) * 4;
            cp_async16(dstA, &A[(size_t)(m0 + lm) * Kk + kt + c],
                       (m0 + lm < Mm) ? 16 : 0);
            uint32_t dstB = smem_base + (stage * 2 * BUF + BUF + lm * AST + c) * 4;
            cp_async16(dstB, &W[(size_t)(n0 + lm) * Kk + kt + c], 16);
        }
        cp_commit();
    };

    load_stage(0, 0);
    load_stage(1, 1);

    for (int it = 0; it < ntiles; it++) {
        if (it + 1 < ntiles) cp_wait<1>(); else cp_wait<0>();
        __syncthreads();
        if (it + 2 < ntiles) {
            int st = it + 2; st -= (st / 3) * 3;
            load_stage(it + 2, st);
        }

        int cs = it - (it / 3) * 3;
        const uint32_t* Ab = smu + cs * 2 * BUF;
        const uint32_t* Bb = Ab + BUF;

        #pragma unroll
        for (int ks = 0; ks < KT; ks += 8) {
            uint32_t af[4][4], bf[4][2];
            #pragma unroll
            for (int mt = 0; mt < 4; mt++) {
                int m = wm * 64 + mt * 16 + g;
                af[mt][0] = Ab[m * AST + ks + t];
                af[mt][1] = Ab[(m + 8) * AST + ks + t];
                af[mt][2] = Ab[m * AST + ks + t + 4];
                af[mt][3] = Ab[(m + 8) * AST + ks + t + 4];
            }
            #pragma unroll
            for (int nt = 0; nt < 4; nt++) {
                int n = wn * 32 + nt * 8 + g;
                bf[nt][0] = Bb[n * AST + ks + t];
                bf[nt][1] = Bb[n * AST + ks + t + 4];
            }
            #pragma unroll
            for (int mt = 0; mt < 4; mt++)
                #pragma unroll
                for (int nt = 0; nt < 4; nt++)
                    mma_tf32(acc[mt][nt], af[mt], bf[nt]);
        }
        __syncthreads();
    }

    // ---- epilogue (vectorized pairs) ----
    #pragma unroll
    for (int mt = 0; mt < 4; mt++) {
        #pragma unroll
        for (int nt = 0; nt < 4; nt++) {
            int n = n0 + wn * 32 + nt * 8 + t * 2;
            float b0 = bias[n], b1 = bias[n + 1];
            #pragma unroll
            for (int half = 0; half < 2; half++) {
                int m = m0 + wm * 64 + mt * 16 + g + half * 8;
                if (m >= Mm) continue;
                float v0 = acc[mt][nt][half * 2 + 0] + b0;
                float v1 = acc[mt][nt][half * 2 + 1] + b1;
                if (GELU) {
                    v0 = 0.5f * v0 * (1.0f + erff(v0 * 0.70710678118654752f));
                    v1 = 0.5f * v1 * (1.0f + erff(v1 * 0.70710678118654752f));
                }
                if (RESID) {
                    float2 r = *(const float2*)&Rz[(size_t)m * Nn + n];
                    v0 += r.x; v1 += r.y;
                }
                if (OUT32) {
                    uint2 o = make_uint2(f2tf32(v0), f2tf32(v1));
                    *(uint2*)&((uint32_t*)C)[(size_t)m * Nn + n] = o;
                } else {
                    *(float2*)&C[(size_t)m * Nn + n] = make_float2(v0, v1);
                }
            }
        }
    }
}

// ---------------- tensor-core flash attention (all tf32 bits) ------------------
#define KST 68
#define ATTN_SMEM (3 * 64 * KST * 4)

__global__ void __launch_bounds__(128) attn_mma_kernel()
{
    extern __shared__ uint32_t asmu[];
    uint32_t* Ks = asmu;
    uint32_t* Vs = asmu + 64 * KST;
    float*    Ps = (float*)(asmu + 2 * 64 * KST);

    int qt = blockIdx.x, h = blockIdx.y, b = blockIdx.z;
    int tid = threadIdx.x;
    int warp = tid >> 5, lane = tid & 31;
    int g = lane >> 2, t = lane & 3;

    int row0 = qt * 64 + warp * 16 + g;
    int row1 = row0 + 8;
    bool v0 = row0 < S, v1 = row1 < S;

    uint32_t smem_base = (uint32_t)__cvta_generic_to_shared(asmu);

    // ---- Q fragments (tf32 bits, unscaled; 1/8 applied to scores) ----
    uint32_t qf[8][4];
    {
        const uint32_t* q0 = g_qkv + ((size_t)(b * S) + (v0 ? row0 : 0)) * (3 * D) + h * DH;
        const uint32_t* q1 = g_qkv + ((size_t)(b * S) + (v1 ? row1 : 0)) * (3 * D) + h * DH;
        #pragma unroll
        for (int ks = 0; ks < 8; ks++) {
            int k0 = ks * 8 + t;
            qf[ks][0] = v0 ? q0[k0] : 0u;
            qf[ks][1] = v1 ? q1[k0] : 0u;
            qf[ks][2] = v0 ? q0[k0 + 4] : 0u;
            qf[ks][3] = v1 ? q1[k0 + 4] : 0u;
        }
    }

    float oacc[8][4];
    #pragma unroll
    for (int i = 0; i < 8; i++)
        #pragma unroll
        for (int c = 0; c < 4; c++) oacc[i][c] = 0.f;
    float m0r = -1e30f, m1r = -1e30f, l0 = 0.f, l1 = 0.f;

    const int NT = (S + 63) / 64;

    for (int kt = 0; kt < NT; kt++) {
        // ---- cp.async K/V tile (zero-fill OOB rows) ----
        #pragma unroll
        for (int i = 0; i < 8; i++) {
            int idx = tid + i * 128;
            int r = idx >> 4, c4 = (idx & 15) * 4;
            int ki = kt * 64 + r;
            int bytes = (ki < S) ? 16 : 0;
            const uint32_t* base = g_qkv +
                ((size_t)(b * S) + (ki < S ? ki : 0)) * (3 * D) + h * DH + c4;
            cp_async16(smem_base + (r * KST + c4) * 4, base + D, bytes);
            cp_async16(smem_base + (64 * KST + r * KST + c4) * 4, base + 2 * D, bytes);
        }
        cp_commit();
        cp_wait<0>();
        __syncthreads();

        // ---- scores S = (Q @ K^T) * 0.125 ----
        float sacc[8][4];
        #pragma unroll
        for (int nt = 0; nt < 8; nt++) {
            #pragma unroll
            for (int c = 0; c < 4; c++) sacc[nt][c] = 0.f;
            #pragma unroll
            for (int ks = 0; ks < 8; ks++) {
                uint32_t bf[2];
                bf[0] = Ks[(nt * 8 + g) * KST + ks * 8 + t];
                bf[1] = Ks[(nt * 8 + g) * KST + ks * 8 + t + 4];
                mma_tf32(sacc[nt], qf[ks], bf);
            }
            #pragma unroll
            for (int c = 0; c < 4; c++) sacc[nt][c] *= 0.125f;
        }

        // ---- mask + online softmax ----
        bool feat0 = row0 >= G, feat1 = row1 >= G;
        float mx0 = -1e30f, mx1 = -1e30f;
        #pragma unroll
        for (int nt = 0; nt < 8; nt++) {
            #pragma unroll
            for (int c = 0; c < 4; c++) {
                int col = kt * 64 + nt * 8 + 2 * t + (c & 1);
                bool bad = (col >= S) || ((c < 2 ? feat0 : feat1) && col < G);
                if (bad) sacc[nt][c] = -1e30f;
            }
            mx0 = fmaxf(mx0, fmaxf(sacc[nt][0], sacc[nt][1]));
            mx1 = fmaxf(mx1, fmaxf(sacc[nt][2], sacc[nt][3]));
        }
        mx0 = fmaxf(mx0, __shfl_xor_sync(0xFFFFFFFFu, mx0, 1));
        mx0 = fmaxf(mx0, __shfl_xor_sync(0xFFFFFFFFu, mx0, 2));
        mx1 = fmaxf(mx1, __shfl_xor_sync(0xFFFFFFFFu, mx1, 1));
        mx1 = fmaxf(mx1, __shfl_xor_sync(0xFFFFFFFFu, mx1, 2));

        float mn0 = fmaxf(m0r, mx0), mn1 = fmaxf(m1r, mx1);
        float sc0 = __expf(m0r - mn0), sc1 = __expf(m1r - mn1);
        m0r = mn0; m1r = mn1;

        float ls0 = 0.f, ls1 = 0.f;
        int prow0 = (warp * 16 + g) * KST;
        int prow1 = (warp * 16 + g + 8) * KST;
        #pragma unroll
        for (int nt = 0; nt < 8; nt++) {
            float p0 = __expf(sacc[nt][0] - mn0);
            float p1 = __expf(sacc[nt][1] - mn0);
            float p2 = __expf(sacc[nt][2] - mn1);
            float p3 = __expf(sacc[nt][3] - mn1);
            ls0 += p0 + p1; ls1 += p2 + p3;
            Ps[prow0 + nt * 8 + 2 * t]     = p0;
            Ps[prow0 + nt * 8 + 2 * t + 1] = p1;
            Ps[prow1 + nt * 8 + 2 * t]     = p2;
            Ps[prow1 + nt * 8 + 2 * t + 1] = p3;
            #pragma unroll
            for (int c = 0; c < 4; c++)
                oacc[nt][c] *= (c < 2) ? sc0 : sc1;
        }
        ls0 += __shfl_xor_sync(0xFFFFFFFFu, ls0, 1);
        ls0 += __shfl_xor_sync(0xFFFFFFFFu, ls0, 2);
        ls1 += __shfl_xor_sync(0xFFFFFFFFu, ls1, 1);
        ls1 += __shfl_xor_sync(0xFFFFFFFFu, ls1, 2);
        l0 = l0 * sc0 + ls0;
        l1 = l1 * sc1 + ls1;
        __syncwarp();

        // ---- O += P @ V ----
        #pragma unroll
        for (int ks = 0; ks < 8; ks++) {
            uint32_t pf[4];
            pf[0] = f2tf32(Ps[prow0 + ks * 8 + t]);
            pf[1] = f2tf32(Ps[prow1 + ks * 8 + t]);
            pf[2] = f2tf32(Ps[prow0 + ks * 8 + t + 4]);
            pf[3] = f2tf32(Ps[prow1 + ks * 8 + t + 4]);
            #pragma unroll
            for (int nt = 0; nt < 8; nt++) {
                uint32_t vf[2];
                vf[0] = Vs[(ks * 8 + t) * KST + nt * 8 + g];
                vf[1] = Vs[(ks * 8 + t + 4) * KST + nt * 8 + g];
                mma_tf32(oacc[nt], pf, vf);
            }
        }
        __syncthreads();
    }

    // ---- write O as tf32 bits ----
    float inv0 = 1.0f / l0, inv1 = 1.0f / l1;
    uint32_t* o0 = g_o + ((size_t)(b * S) + row0) * D + h * DH;
    uint32_t* o1 = g_o + ((size_t)(b * S) + row1) * D + h * DH;
    #pragma unroll
    for (int nt = 0; nt < 8; nt++) {
        int cbase = nt * 8 + 2 * t;
        if (v0) {
            o0[cbase]     = f2tf32(oacc[nt][0] * inv0);
            o0[cbase + 1] = f2tf32(oacc[nt][1] * inv0);
        }
        if (v1) {
            o1[cbase]     = f2tf32(oacc[nt][2] * inv1);
            o1[cbase + 1] = f2tf32(oacc[nt][3] * inv1);
        }
    }
}

// ---------------- scatter final outputs ----------------------------------------
__global__ void __launch_bounds__(256) scatter_out_kernel(float* __restrict__ out)
{
    int idx = blockIdx.x * 256 + threadIdx.x;
    const int FEAT = BB * D * HW;
    const int CTX  = BB * D;
    const int REG  = BB * 4 * D;
    if (idx < FEAT) {
        int b = idx / (D * HW);
        int r = idx % (D * HW);
        int k = r / HW;
        int pix = r % HW;
        out[idx] = g_y2[((size_t)(b * S + G + pix)) * D + k];
    } else if (idx < FEAT + CTX) {
        int i2 = idx - FEAT;
        int b = i2 / D, k = i2 % D;
        out[idx] = g_y2[((size_t)(b * S)) * D + k];
    } else if (idx < FEAT + CTX + REG) {
        int i3 = idx - FEAT - CTX;
        int b = i3 / (4 * D);
        int rr = (i3 / D) % 4;
        int k = i3 % D;
        out[idx] = g_y2[((size_t)(b * S + 1 + rr)) * D + k];
    }
}

// ---------------- host launcher -------------------------------------------------
extern "C" void kernel_launch(void* const* d_in, const int* in_sizes, int n_in,
                              void* d_out, int out_size)
{
    const float* x    = (const float*)d_in[0];
    const float* ctx  = (const float*)d_in[1];
    const float* regs = (const float*)d_in[2];
    const float* wqkv = (const float*)d_in[3];
    const float* bqkv = (const float*)d_in[4];
    const float* wout = (const float*)d_in[5];
    const float* bout = (const float*)d_in[6];
    const float* ln1s = (const float*)d_in[7];
    const float* ln1b = (const float*)d_in[8];
    const float* ln2s = (const float*)d_in[9];
    const float* ln2b = (const float*)d_in[10];
    const float* w1   = (const float*)d_in[11];
    const float* b1   = (const float*)d_in[12];
    const float* w2   = (const float*)d_in[13];
    const float* b2   = (const float*)d_in[14];
    float* out = (float*)d_out;
    (void)in_sizes; (void)n_in; (void)out_size;

    uint32_t *xwt32, *qkv, *o, *z32, *h32;
    uint32_t *wqkv32, *wout32, *w132, *w232;
    float *xwt, *y, *y2;
    cudaGetSymbolAddress((void**)&xwt,    g_xwt);
    cudaGetSymbolAddress((void**)&xwt32,  g_xwt32);
    cudaGetSymbolAddress((void**)&qkv,    g_qkv);
    cudaGetSymbolAddress((void**)&o,      g_o);
    cudaGetSymbolAddress((void**)&y,      g_y);
    cudaGetSymbolAddress((void**)&z32,    g_z32);
    cudaGetSymbolAddress((void**)&h32,    g_h32);
    cudaGetSymbolAddress((void**)&y2,     g_y2);
    cudaGetSymbolAddress((void**)&wqkv32, g_wqkv32);
    cudaGetSymbolAddress((void**)&wout32, g_wout32);
    cudaGetSymbolAddress((void**)&w132,   g_w132);
    cudaGetSymbolAddress((void**)&w232,   g_w232);

    cudaFuncSetAttribute(gemm_tf32<false, false, true>,
        cudaFuncAttributeMaxDynamicSharedMemorySize, GEMM_SMEM);
    cudaFuncSetAttribute(gemm_tf32<false, true, false>,
        cudaFuncAttributeMaxDynamicSharedMemorySize, GEMM_SMEM);
    cudaFuncSetAttribute(gemm_tf32<true, false, true>,
        cudaFuncAttributeMaxDynamicSharedMemorySize, GEMM_SMEM);
    cudaFuncSetAttribute(attn_mma_kernel,
        cudaFuncAttributeMaxDynamicSharedMemorySize, ATTN_SMEM);

    const int M = M_TOT;
    const int MG = (M + 127) / 128;            // 65

    convert_weights_kernel<<<(4 * D * D + 255) / 256, 256>>>(wqkv, wout, w1, w2);

    build_xwt_kernel<<<M, 256>>>(x, ctx, regs, ln1s, ln1b);

    gemm_tf32<false, false, true><<<dim3(3 * D / 128, MG), 256, GEMM_SMEM>>>(
        xwt32, wqkv32, bqkv, nullptr, (float*)qkv, M, 3 * D, D);

    attn_mma_kernel<<<dim3((S + 63) / 64, NH, BB), 128, ATTN_SMEM>>>();

    gemm_tf32<false, true, false><<<dim3(D / 128, MG), 256, GEMM_SMEM>>>(
        o, wout32, bout, xwt, y, M, D, D);

    ln_kernel<<<M, 256>>>(y, ln2s, ln2b, z32);

    gemm_tf32<true, false, true><<<dim3(4 * D / 128, MG), 256, GEMM_SMEM>>>(
        z32, w132, b1, nullptr, (float*)h32, M, 4 * D, D);

    gemm_tf32<false, true, false><<<dim3(D / 128, MG), 256, GEMM_SMEM>>>(
        h32, w232, b2, y, y2, M, D, 4 * D);

    const int TOT = BB * D * HW + BB * D + BB * 4 * D;
    scatter_out_kernel<<<(TOT + 255) / 256, 256>>>(out);
}